// round 11
// baseline (speedup 1.0000x reference)
#include <cuda_runtime.h>
#include <cuda_bf16.h>
#include <cuda_fp16.h>
#include <math.h>
#include <stdint.h>

// ---------------- problem constants ----------------
#define BATCH 4
#define SEQ 4096
#define DMODEL 1024
#define NHEAD 16
#define DH 64
#define MTOK (BATCH*SEQ)   // 16384
#define ACT_ELEMS ((size_t)MTOK * DMODEL)
#define W_ELEMS   ((size_t)DMODEL * DMODEL)

// ---------------- scratch (__device__ globals; allocation-free rule) ------
__device__ float g_q [ACT_ELEMS];
__device__ float g_k [ACT_ELEMS];
__device__ float g_v [ACT_ELEMS];
// slice 0: Q acts fp16-hi (later reused as ao fp16), 1: K acts fp16-hi, 2: V acts fp16
__device__ __half g_xh[3 * ACT_ELEMS];
__device__ __half g_xl[3 * ACT_ELEMS];   // lo splits for slices 0,1 only
// slice 0: Wq-hi, 1: Wk-hi, 2: Wv (single), 3: Wo (single) — all fp16
__device__ __half g_wh[4 * W_ELEMS];
__device__ __half g_wl[4 * W_ELEMS];     // lo used only for slices 0,1

// ---------------- small PTX helpers (base ISA only) ----------------
__device__ __forceinline__ uint32_t smem_u32(const void* p) {
    uint32_t a;
    asm("{ .reg .u64 t; cvta.to.shared.u64 t, %1; cvt.u32.u64 %0, t; }" : "=r"(a) : "l"(p));
    return a;
}

#define CP_ASYNC16(saddr, gptr) \
    asm volatile("cp.async.cg.shared.global [%0], [%1], 16;" :: "r"((uint32_t)(saddr)), "l"(gptr))
#define CP_COMMIT() asm volatile("cp.async.commit_group;" ::: "memory")
#define CP_WAIT(n)  asm volatile("cp.async.wait_group %0;" :: "n"(n) : "memory")

#define LDSM_X4(r, addr) \
    asm volatile("ldmatrix.sync.aligned.m8n8.x4.shared.b16 {%0,%1,%2,%3}, [%4];" \
        : "=r"((r)[0]), "=r"((r)[1]), "=r"((r)[2]), "=r"((r)[3]) : "r"(addr))

// fp16 inputs, fp32 accumulate
__device__ __forceinline__ void mma16816h(float* d, const uint32_t* a, const uint32_t* b) {
    asm volatile(
        "mma.sync.aligned.m16n8k16.row.col.f32.f16.f16.f32 "
        "{%0,%1,%2,%3}, {%4,%5,%6,%7}, {%8,%9}, {%0,%1,%2,%3};"
        : "+f"(d[0]), "+f"(d[1]), "+f"(d[2]), "+f"(d[3])
        : "r"(a[0]), "r"(a[1]), "r"(a[2]), "r"(a[3]), "r"(b[0]), "r"(b[1]));
}

// fp16 inputs, fp16 accumulate (correction products; possibly 2x rate)
__device__ __forceinline__ void mma16816hh(uint32_t* d, const uint32_t* a, const uint32_t* b) {
    asm volatile(
        "mma.sync.aligned.m16n8k16.row.col.f16.f16.f16.f16 "
        "{%0,%1}, {%2,%3,%4,%5}, {%6,%7}, {%0,%1};"
        : "+r"(d[0]), "+r"(d[1])
        : "r"(a[0]), "r"(a[1]), "r"(a[2]), "r"(a[3]), "r"(b[0]), "r"(b[1]));
}

// ---------------- fast exp on the FMA pipe (no MUFU) ----------------
__device__ __forceinline__ float fast_exp(float x) {
    x = fmaxf(x, -80.0f);                 // exp(-80) ~ 1.8e-35, negligible vs sum >= 1
    float t = x * 1.44269504f;            // log2(e)
    int   i = __float2int_rn(t);
    float f = t - (float)i;               // f in [-0.5, 0.5]
    float p =           0.0013397664f;
    p = fmaf(p, f, 0.0096189856f);
    p = fmaf(p, f, 0.0555054000f);
    p = fmaf(p, f, 0.2402265200f);
    p = fmaf(p, f, 0.6931471800f);
    p = fmaf(p, f, 1.0f);
    int e1 = i >> 1;                      // split exponent: both halves >= -63
    int e2 = i - e1;
    float s1 = __int_as_float((e1 + 127) << 23);
    float s2 = __int_as_float((e2 + 127) << 23);
    return (p * s1) * s2;
}

// ---------------- splits fp32 -> fp16 hi/lo ----------------
__device__ __forceinline__ void split4_f16(float4 x, uint2& H, uint2& L) {
    __half2 h01 = __floats2half2_rn(x.x, x.y);
    __half2 h23 = __floats2half2_rn(x.z, x.w);
    float2 f01 = __half22float2(h01);
    float2 f23 = __half22float2(h23);
    __half2 l01 = __floats2half2_rn(x.x - f01.x, x.y - f01.y);
    __half2 l23 = __floats2half2_rn(x.z - f23.x, x.w - f23.y);
    H.x = *reinterpret_cast<unsigned int*>(&h01);
    H.y = *reinterpret_cast<unsigned int*>(&h23);
    L.x = *reinterpret_cast<unsigned int*>(&l01);
    L.y = *reinterpret_cast<unsigned int*>(&l23);
}

__device__ __forceinline__ uint2 pack4_f16(float4 x) {
    __half2 h01 = __floats2half2_rn(x.x, x.y);
    __half2 h23 = __floats2half2_rn(x.z, x.w);
    uint2 H;
    H.x = *reinterpret_cast<unsigned int*>(&h01);
    H.y = *reinterpret_cast<unsigned int*>(&h23);
    return H;
}

// acts: y=0 query (split), y=1 key_ (split), y=2 value (single)
__global__ void __launch_bounds__(256) split_acts_kernel(
    const float4* __restrict__ s0, const float4* __restrict__ s1, const float4* __restrict__ s2,
    uint2* __restrict__ hi, uint2* __restrict__ lo, int n4)
{
    int i = blockIdx.x * blockDim.x + threadIdx.x;
    if (i >= n4) return;
    int which = blockIdx.y;
    if (which < 2) {
        uint2 H, L;
        split4_f16(which == 0 ? s0[i] : s1[i], H, L);
        hi[(size_t)which * n4 + i] = H;
        lo[(size_t)which * n4 + i] = L;
    } else {
        hi[(size_t)2 * n4 + i] = pack4_f16(s2[i]);
    }
}

// weights: y=0 Wq / y=1 Wk (split); y=2 Wv / y=3 Wo (single, hi only)
__global__ void __launch_bounds__(256) split_w_kernel(
    const float4* __restrict__ s0, const float4* __restrict__ s1,
    const float4* __restrict__ s2, const float4* __restrict__ s3,
    uint2* __restrict__ hi, uint2* __restrict__ lo, int n4)
{
    int i = blockIdx.x * blockDim.x + threadIdx.x;
    if (i >= n4) return;
    int which = blockIdx.y;
    if (which < 2) {
        uint2 H, L;
        split4_f16(which == 0 ? s0[i] : s1[i], H, L);
        hi[(size_t)which * n4 + i] = H;
        lo[(size_t)which * n4 + i] = L;
    } else {
        hi[(size_t)which * n4 + i] = pack4_f16(which == 2 ? s2[i] : s3[i]);
    }
}

// ================= fp16x3 GEMM (Q/K projections) ==========================
// C = Ah*Wh (f32 acc) + [Ah*Wl + Al*Wh] (f16 acc, merged in epilogue) + bias.
// Dropped Al*Wl term ~2^-22 rel. CTA 128x128, K-chunk 64, 3-stage cp.async.
#define GBM 128
#define GBN 128
#define GBK 64
#define KDIM DMODEL
#define NCHUNK (KDIM/GBK)      // 16
#define STAGE_BYTES 65536      // Ah 16K | Al 16K | Bh 16K | Bl 16K
#define A_HI 0
#define A_LO 16384
#define B_HI 32768
#define B_LO 49152
#define NSTAGE 3
#define GSMEM_TOTAL (NSTAGE*STAGE_BYTES)   // 196608

__global__ void __launch_bounds__(256, 1) gemm_f16x3(
    const __half* __restrict__ Ah, const __half* __restrict__ Al,
    const __half* __restrict__ Wh, const __half* __restrict__ Wl,
    const float* __restrict__ bias, float* __restrict__ C)
{
    extern __shared__ char smem[];
    const uint32_t sb = smem_u32(smem);
    const int tid = threadIdx.x;
    const int m0 = blockIdx.y * GBM;
    const int n0 = blockIdx.x * GBN;

    const int l  = tid & 31;
    const int w  = tid >> 5;
    const int wm = (w & 3) * 32;
    const int wn = (w >> 2) * 64;

    const int rowA  = (l & 7) + ((l >> 3) & 1) * 8;
    const int kselA = (l >> 4) & 1;
    const int rowB  = (l & 7) + ((l >> 4) & 1) * 8;
    const int kselB = (l >> 3) & 1;

    float acc[2][8][4];
    uint32_t acc16[2][8][2];   // f16x2 correction accumulators
#pragma unroll
    for (int a = 0; a < 2; a++)
#pragma unroll
        for (int b = 0; b < 8; b++) {
#pragma unroll
            for (int c = 0; c < 4; c++) acc[a][b][c] = 0.0f;
            acc16[a][b][0] = 0u; acc16[a][b][1] = 0u;
        }

    auto load_chunk = [&](int st, int c) {
        uint32_t base = sb + st * STAGE_BYTES;
        int k0 = c * GBK;
#pragma unroll
        for (int it = 0; it < 4; it++) {
            int idx = tid + it * 256;
            int r  = idx >> 3;
            int ch = idx & 7;
            uint32_t sw = (uint32_t)(r * 128 + ((ch ^ (r & 7)) * 16));
            size_t gA = (size_t)(m0 + r) * KDIM + k0 + ch * 8;
            size_t gB = (size_t)(n0 + r) * KDIM + k0 + ch * 8;
            CP_ASYNC16(base + A_HI + sw, Ah + gA);
            CP_ASYNC16(base + A_LO + sw, Al + gA);
            CP_ASYNC16(base + B_HI + sw, Wh + gB);
            CP_ASYNC16(base + B_LO + sw, Wl + gB);
        }
    };

    load_chunk(0, 0); CP_COMMIT();
    load_chunk(1, 1); CP_COMMIT();

    uint32_t a_h[2][4], a_l[2][4], b_h[4][4], b_l[4][4];

    for (int c = 0; c < NCHUNK; c++) {
        int st = c % NSTAGE;
        uint32_t base = sb + st * STAGE_BYTES;
        if (c + 2 < NCHUNK) { CP_WAIT(1); } else { CP_WAIT(0); }
        __syncthreads();
        if (c + 2 < NCHUNK) {
            load_chunk((c + 2) % NSTAGE, c + 2); CP_COMMIT();
        }
#pragma unroll
        for (int s = 0; s < 4; s++) {
#pragma unroll
            for (int mt = 0; mt < 2; mt++) {
                int row = wm + mt * 16 + rowA;
                int ch  = (s * 2 + kselA) ^ (row & 7);
                uint32_t off = (uint32_t)(row * 128 + ch * 16);
                LDSM_X4(a_h[mt], base + A_HI + off);
                LDSM_X4(a_l[mt], base + A_LO + off);
            }
#pragma unroll
            for (int ng = 0; ng < 4; ng++) {
                int row = wn + ng * 16 + rowB;
                int ch  = (s * 2 + kselB) ^ (row & 7);
                uint32_t off = (uint32_t)(row * 128 + ch * 16);
                LDSM_X4(b_h[ng], base + B_HI + off);
                LDSM_X4(b_l[ng], base + B_LO + off);
            }
            // main product: f32 accumulate
#pragma unroll
            for (int mt = 0; mt < 2; mt++)
#pragma unroll
                for (int ng = 0; ng < 4; ng++) {
                    mma16816h(acc[mt][ng * 2 + 0], a_h[mt], &b_h[ng][0]);
                    mma16816h(acc[mt][ng * 2 + 1], a_h[mt], &b_h[ng][2]);
                }
            // correction products: f16 accumulate
#pragma unroll
            for (int mt = 0; mt < 2; mt++)
#pragma unroll
                for (int ng = 0; ng < 4; ng++) {
                    mma16816hh(acc16[mt][ng * 2 + 0], a_h[mt], &b_l[ng][0]);
                    mma16816hh(acc16[mt][ng * 2 + 1], a_h[mt], &b_l[ng][2]);
                }
#pragma unroll
            for (int mt = 0; mt < 2; mt++)
#pragma unroll
                for (int ng = 0; ng < 4; ng++) {
                    mma16816hh(acc16[mt][ng * 2 + 0], a_l[mt], &b_h[ng][0]);
                    mma16816hh(acc16[mt][ng * 2 + 1], a_l[mt], &b_h[ng][2]);
                }
        }
    }

    const int g  = l >> 2;
    const int tg = l & 3;
#pragma unroll
    for (int mt = 0; mt < 2; mt++) {
#pragma unroll
        for (int nt = 0; nt < 8; nt++) {
            // merge f16 corrections into f32 accumulators
            __half2 c0 = *reinterpret_cast<__half2*>(&acc16[mt][nt][0]);
            __half2 c1 = *reinterpret_cast<__half2*>(&acc16[mt][nt][1]);
            float2 f0 = __half22float2(c0);
            float2 f1 = __half22float2(c1);
            int n = n0 + wn + nt * 8 + tg * 2;
            float bx = bias[n], by = bias[n + 1];
            int mA = m0 + wm + mt * 16 + g;
            float2 lo = make_float2(acc[mt][nt][0] + f0.x + bx, acc[mt][nt][1] + f0.y + by);
            float2 hi = make_float2(acc[mt][nt][2] + f1.x + bx, acc[mt][nt][3] + f1.y + by);
            *(float2*)(C + (size_t)mA * DMODEL + n)       = lo;
            *(float2*)(C + (size_t)(mA + 8) * DMODEL + n) = hi;
        }
    }
}

// ================= fp16x1 GEMM: C = A @ W^T + bias (V/O projections) ======
#define H1STAGE_BYTES 32768    // A 16K | B 16K
#define H1_A 0
#define H1_B 16384
#define H1SMEM_TOTAL (NSTAGE*H1STAGE_BYTES)  // 98304

__global__ void __launch_bounds__(256, 1) gemm_fp16x1(
    const __half* __restrict__ A, const __half* __restrict__ W,
    const float* __restrict__ bias, float* __restrict__ C)
{
    extern __shared__ char smem[];
    const uint32_t sb = smem_u32(smem);
    const int tid = threadIdx.x;
    const int m0 = blockIdx.y * GBM;
    const int n0 = blockIdx.x * GBN;

    const int l  = tid & 31;
    const int w  = tid >> 5;
    const int wm = (w & 3) * 32;
    const int wn = (w >> 2) * 64;

    const int rowA  = (l & 7) + ((l >> 3) & 1) * 8;
    const int kselA = (l >> 4) & 1;
    const int rowB  = (l & 7) + ((l >> 4) & 1) * 8;
    const int kselB = (l >> 3) & 1;

    float acc[2][8][4];
#pragma unroll
    for (int a = 0; a < 2; a++)
#pragma unroll
        for (int b = 0; b < 8; b++)
#pragma unroll
            for (int c = 0; c < 4; c++) acc[a][b][c] = 0.0f;

    auto load_chunk = [&](int st, int c) {
        uint32_t base = sb + st * H1STAGE_BYTES;
        int k0 = c * GBK;
#pragma unroll
        for (int it = 0; it < 4; it++) {
            int idx = tid + it * 256;
            int r  = idx >> 3;
            int ch = idx & 7;
            uint32_t sw = (uint32_t)(r * 128 + ((ch ^ (r & 7)) * 16));
            size_t gA = (size_t)(m0 + r) * KDIM + k0 + ch * 8;
            size_t gB = (size_t)(n0 + r) * KDIM + k0 + ch * 8;
            CP_ASYNC16(base + H1_A + sw, A + gA);
            CP_ASYNC16(base + H1_B + sw, W + gB);
        }
    };

    load_chunk(0, 0); CP_COMMIT();
    load_chunk(1, 1); CP_COMMIT();

    uint32_t ra[2][4], rb[4][4];

    for (int c = 0; c < NCHUNK; c++) {
        int st = c % NSTAGE;
        uint32_t base = sb + st * H1STAGE_BYTES;
        if (c + 2 < NCHUNK) { CP_WAIT(1); } else { CP_WAIT(0); }
        __syncthreads();
        if (c + 2 < NCHUNK) {
            load_chunk((c + 2) % NSTAGE, c + 2); CP_COMMIT();
        }
#pragma unroll
        for (int s = 0; s < 4; s++) {
#pragma unroll
            for (int mt = 0; mt < 2; mt++) {
                int row = wm + mt * 16 + rowA;
                int ch  = (s * 2 + kselA) ^ (row & 7);
                LDSM_X4(ra[mt], base + H1_A + (uint32_t)(row * 128 + ch * 16));
            }
#pragma unroll
            for (int ng = 0; ng < 4; ng++) {
                int row = wn + ng * 16 + rowB;
                int ch  = (s * 2 + kselB) ^ (row & 7);
                LDSM_X4(rb[ng], base + H1_B + (uint32_t)(row * 128 + ch * 16));
            }
#pragma unroll
            for (int mt = 0; mt < 2; mt++)
#pragma unroll
                for (int ng = 0; ng < 4; ng++) {
                    mma16816h(acc[mt][ng * 2 + 0], ra[mt], &rb[ng][0]);
                    mma16816h(acc[mt][ng * 2 + 1], ra[mt], &rb[ng][2]);
                }
        }
    }

    const int g  = l >> 2;
    const int tg = l & 3;
#pragma unroll
    for (int mt = 0; mt < 2; mt++) {
#pragma unroll
        for (int nt = 0; nt < 8; nt++) {
            int n = n0 + wn + nt * 8 + tg * 2;
            float bx = bias[n], by = bias[n + 1];
            int mA = m0 + wm + mt * 16 + g;
            float2 lo = make_float2(acc[mt][nt][0] + bx, acc[mt][nt][1] + by);
            float2 hi = make_float2(acc[mt][nt][2] + bx, acc[mt][nt][3] + by);
            *(float2*)(C + (size_t)mA * DMODEL + n)       = lo;
            *(float2*)(C + (size_t)(mA + 8) * DMODEL + n) = hi;
        }
    }
}

// ---------------- per-token attention, online softmax, FMA-pipe exp ------
__global__ __launch_bounds__(128) void attn_per_token(
    const float* __restrict__ q, const float* __restrict__ k,
    const float* __restrict__ v, __half* __restrict__ ao)
{
    const int half_ = threadIdx.x >> 6;
    const int t = blockIdx.x * 2 + half_;
    const int i = threadIdx.x & 63;

    __shared__ float sk[2][DMODEL];
    __shared__ float sv[2][DMODEL];

    const float* kt = k + (size_t)t * DMODEL;
    const float* vt = v + (size_t)t * DMODEL;
#pragma unroll
    for (int f = i; f < 256; f += 64) {
        ((float4*)sk[half_])[f] = ((const float4*)kt)[f];
        ((float4*)sv[half_])[f] = ((const float4*)vt)[f];
    }
    __syncthreads();

    float4 q4[4];
    const float4* qt = (const float4*)(q + (size_t)t * DMODEL + i * NHEAD);
#pragma unroll
    for (int hg = 0; hg < 4; hg++) {
        float4 tq = qt[hg];
        q4[hg] = make_float4(tq.x * 32.0f, tq.y * 32.0f, tq.z * 32.0f, tq.w * 32.0f);
    }

    const float4* k4 = (const float4*)sk[half_];
    const float4* v4 = (const float4*)sv[half_];

    float m = -1e30f, ssum = 0.0f;
    float4 o4[4];
#pragma unroll
    for (int hg = 0; hg < 4; hg++) o4[hg] = make_float4(0.f, 0.f, 0.f, 0.f);

#pragma unroll
    for (int jc = 0; jc < 4; jc++) {
        float sc[16];
        float cm = -1e30f;
#pragma unroll
        for (int jj = 0; jj < 16; jj++) {
            int j = jc * 16 + jj;
            float4 a = make_float4(0.f, 0.f, 0.f, 0.f);
#pragma unroll
            for (int hg = 0; hg < 4; hg++) {
                float4 kk = k4[j * 4 + hg];
                a.x = fmaf(q4[hg].x, kk.x, a.x);
                a.y = fmaf(q4[hg].y, kk.y, a.y);
                a.z = fmaf(q4[hg].z, kk.z, a.z);
                a.w = fmaf(q4[hg].w, kk.w, a.w);
            }
            sc[jj] = (a.x + a.y) + (a.z + a.w);
            cm = fmaxf(cm, sc[jj]);
        }
        float nm = fmaxf(m, cm);
        float scale = fast_exp(m - nm);
        ssum *= scale;
#pragma unroll
        for (int hg = 0; hg < 4; hg++) {
            o4[hg].x *= scale; o4[hg].y *= scale;
            o4[hg].z *= scale; o4[hg].w *= scale;
        }
#pragma unroll
        for (int jj = 0; jj < 16; jj++) {
            int j = jc * 16 + jj;
            float p = fast_exp(sc[jj] - nm);
            ssum += p;
#pragma unroll
            for (int hg = 0; hg < 4; hg++) {
                float4 vv = v4[j * 4 + hg];
                o4[hg].x = fmaf(p, vv.x, o4[hg].x);
                o4[hg].y = fmaf(p, vv.y, o4[hg].y);
                o4[hg].z = fmaf(p, vv.z, o4[hg].z);
                o4[hg].w = fmaf(p, vv.w, o4[hg].w);
            }
        }
        m = nm;
    }

    const float inv = 1.0f / ssum;
    uint32_t h8[8];
#pragma unroll
    for (int hg = 0; hg < 4; hg++) {
        __half2 p0 = __floats2half2_rn(o4[hg].x * inv, o4[hg].y * inv);
        __half2 p1 = __floats2half2_rn(o4[hg].z * inv, o4[hg].w * inv);
        h8[hg * 2 + 0] = *reinterpret_cast<uint32_t*>(&p0);
        h8[hg * 2 + 1] = *reinterpret_cast<uint32_t*>(&p1);
    }
    size_t obase = (size_t)t * DMODEL + i * NHEAD;
    *(uint4*)(ao + obase)     = make_uint4(h8[0], h8[1], h8[2], h8[3]);
    *(uint4*)(ao + obase + 8) = make_uint4(h8[4], h8[5], h8[6], h8[7]);
}

// ---------------- launch ----------------
extern "C" void kernel_launch(void* const* d_in, const int* in_sizes, int n_in,
                              void* d_out, int out_size)
{
    const float* query = (const float*)d_in[0];
    const float* key_  = (const float*)d_in[1];
    const float* value = (const float*)d_in[2];
    const float* Wq    = (const float*)d_in[3];
    const float* bq    = (const float*)d_in[4];
    const float* Wk    = (const float*)d_in[5];
    const float* bk    = (const float*)d_in[6];
    const float* Wv    = (const float*)d_in[7];
    const float* bv    = (const float*)d_in[8];
    const float* Wo    = (const float*)d_in[9];
    const float* bo    = (const float*)d_in[10];
    float* out = (float*)d_out;

    float *q, *k, *v;
    __half *xh, *xl, *wh, *wl;
    cudaGetSymbolAddress((void**)&q,  g_q);
    cudaGetSymbolAddress((void**)&k,  g_k);
    cudaGetSymbolAddress((void**)&v,  g_v);
    cudaGetSymbolAddress((void**)&xh, g_xh);
    cudaGetSymbolAddress((void**)&xl, g_xl);
    cudaGetSymbolAddress((void**)&wh, g_wh);
    cudaGetSymbolAddress((void**)&wl, g_wl);

    cudaFuncSetAttribute(gemm_f16x3,  cudaFuncAttributeMaxDynamicSharedMemorySize, GSMEM_TOTAL);
    cudaFuncSetAttribute(gemm_fp16x1, cudaFuncAttributeMaxDynamicSharedMemorySize, H1SMEM_TOTAL);

    const int nAct4 = (int)(ACT_ELEMS / 4);
    const int nW4   = (int)(W_ELEMS / 4);
    dim3 sgA((nAct4 + 255) / 256, 3);
    dim3 sgW((nW4 + 255) / 256, 4);
    dim3 ggrid(DMODEL / GBN, MTOK / GBM);   // (8, 128)

    split_acts_kernel<<<sgA, 256>>>((const float4*)query, (const float4*)key_,
                                    (const float4*)value, (uint2*)xh, (uint2*)xl, nAct4);
    split_w_kernel<<<sgW, 256>>>((const float4*)Wq, (const float4*)Wk,
                                 (const float4*)Wv, (const float4*)Wo,
                                 (uint2*)wh, (uint2*)wl, nW4);

    // Q, K projections: fp16x3 (f16-acc corrections)
    gemm_f16x3<<<ggrid, 256, GSMEM_TOTAL>>>(xh,             xl,             wh,           wl,           bq, q);
    gemm_f16x3<<<ggrid, 256, GSMEM_TOTAL>>>(xh + ACT_ELEMS, xl + ACT_ELEMS, wh + W_ELEMS, wl + W_ELEMS, bk, k);
    // V projection: fp16 single product
    gemm_fp16x1<<<ggrid, 256, H1SMEM_TOTAL>>>(xh + 2 * ACT_ELEMS, wh + 2 * W_ELEMS, bv, v);

    // attention: writes ao fp16 into slice 0 of xh
    attn_per_token<<<MTOK / 2, 128>>>(q, k, v, (__half*)xh);

    // O projection: fp16 single product
    gemm_fp16x1<<<ggrid, 256, H1SMEM_TOTAL>>>(xh, wh + 3 * W_ELEMS, bo, out);
}